// round 2
// baseline (speedup 1.0000x reference)
#include <cuda_runtime.h>
#include <math.h>

// Problem constants (fixed shapes for this dataset entry)
#define N_ROWS 4096
#define DIM    512
#define VOCAB  128000

// GEMM tiling
#define BM 128
#define BN 128
#define BK 16
#define TM 8
#define TN 8
#define NTHREADS 256
#define NCOLTILES (VOCAB / BN)   // 1000

// Scratch: per (row, col-tile) partial logsumexp state (max, sumexp)
__device__ float2 g_partials[(size_t)N_ROWS * NCOLTILES];  // 32 MB
__device__ float  g_rowloss[N_ROWS];

// ---------------------------------------------------------------------------
// Kernel 1: C[m, v] = E[m,:] . W[v,:] + b[v]  -> logits, plus fused per-tile
// partial (rowmax, sum exp(x - rowmax)) written to g_partials.
// NOTE: `logits` base is only 4-byte aligned (it is d_out + 1 float, because
// the flattened output pytree is (loss, logits)). ALL logits accesses must be
// scalar 32-bit.
// ---------------------------------------------------------------------------
__global__ __launch_bounds__(NTHREADS) void gemm_ce_kernel(
    const float* __restrict__ E,
    const float* __restrict__ W,
    const float* __restrict__ bias,
    float* __restrict__ logits)
{
    __shared__ float sE[BK][BM];
    __shared__ float sW[BK][BN];
    __shared__ float sred[BM][17];   // padded row-reduction buffer
    __shared__ float sRowMax[BM];

    const int tid = threadIdx.x;
    const int tx = tid & 15;         // 0..15 -> 8 cols each
    const int ty = tid >> 4;         // 0..15 -> 8 rows each
    const int blockN = blockIdx.x * BN;
    const int blockM = blockIdx.y * BM;

    float acc[TM][TN];
    #pragma unroll
    for (int i = 0; i < TM; i++)
        #pragma unroll
        for (int j = 0; j < TN; j++) acc[i][j] = 0.0f;

    for (int k0 = 0; k0 < DIM; k0 += BK) {
        // Load tiles: 128 rows x 16 k floats = 512 float4 each; 2 per thread.
        #pragma unroll
        for (int i = 0; i < 2; i++) {
            int idx = tid + i * NTHREADS;   // 0..511
            int row = idx >> 2;
            int kq  = idx & 3;
            float4 v = *(const float4*)&E[(size_t)(blockM + row) * DIM + k0 + kq * 4];
            sE[kq * 4 + 0][row] = v.x;
            sE[kq * 4 + 1][row] = v.y;
            sE[kq * 4 + 2][row] = v.z;
            sE[kq * 4 + 3][row] = v.w;
            float4 w = *(const float4*)&W[(size_t)(blockN + row) * DIM + k0 + kq * 4];
            sW[kq * 4 + 0][row] = w.x;
            sW[kq * 4 + 1][row] = w.y;
            sW[kq * 4 + 2][row] = w.z;
            sW[kq * 4 + 3][row] = w.w;
        }
        __syncthreads();

        #pragma unroll
        for (int k = 0; k < BK; k++) {
            float4 a0 = *(const float4*)&sE[k][ty * 8];
            float4 a1 = *(const float4*)&sE[k][ty * 8 + 4];
            float4 b0 = *(const float4*)&sW[k][tx * 8];
            float4 b1 = *(const float4*)&sW[k][tx * 8 + 4];
            float a[TM] = {a0.x, a0.y, a0.z, a0.w, a1.x, a1.y, a1.z, a1.w};
            float bb[TN] = {b0.x, b0.y, b0.z, b0.w, b1.x, b1.y, b1.z, b1.w};
            #pragma unroll
            for (int i = 0; i < TM; i++)
                #pragma unroll
                for (int j = 0; j < TN; j++)
                    acc[i][j] = fmaf(a[i], bb[j], acc[i][j]);
        }
        __syncthreads();
    }

    // Add bias, store logits (SCALAR stores: base is 4B-aligned only).
    float bv[TN];
    #pragma unroll
    for (int j = 0; j < TN; j++) bv[j] = bias[blockN + tx * 8 + j];

    #pragma unroll
    for (int i = 0; i < TM; i++) {
        #pragma unroll
        for (int j = 0; j < TN; j++) acc[i][j] += bv[j];
        size_t off = (size_t)(blockM + ty * 8 + i) * VOCAB + blockN + tx * 8;
        #pragma unroll
        for (int j = 0; j < TN; j++)
            logits[off + j] = acc[i][j];
    }

    // ---- Fused partial logsumexp over this 128-wide column tile ----
    // Phase 1: row max
    #pragma unroll
    for (int i = 0; i < TM; i++) {
        float m = acc[i][0];
        #pragma unroll
        for (int j = 1; j < TN; j++) m = fmaxf(m, acc[i][j]);
        sred[ty * 8 + i][tx] = m;
    }
    __syncthreads();
    if (tid < BM) {
        float m = sred[tid][0];
        #pragma unroll
        for (int t = 1; t < 16; t++) m = fmaxf(m, sred[tid][t]);
        sRowMax[tid] = m;
    }
    __syncthreads();

    // Phase 2: sum exp(x - rowmax)
    float rm[TM];
    #pragma unroll
    for (int i = 0; i < TM; i++) rm[i] = sRowMax[ty * 8 + i];
    #pragma unroll
    for (int i = 0; i < TM; i++) {
        float s = 0.0f;
        #pragma unroll
        for (int j = 0; j < TN; j++) s += __expf(acc[i][j] - rm[i]);
        sred[ty * 8 + i][tx] = s;
    }
    __syncthreads();
    if (tid < BM) {
        float s = sred[tid][0];
        #pragma unroll
        for (int t = 1; t < 16; t++) s += sred[tid][t];
        g_partials[(size_t)(blockM + tid) * NCOLTILES + blockIdx.x] =
            make_float2(sRowMax[tid], s);
    }
}

// ---------------------------------------------------------------------------
// Kernel 2: per-row merge of NCOLTILES partials -> logsumexp; gather target
// logit; per-row loss.  Target dtype hedged: jax may emit int64 or int32.
// ---------------------------------------------------------------------------
__global__ __launch_bounds__(256) void row_reduce_kernel(
    const float* __restrict__ logits,
    const int*   __restrict__ tgt32)
{
    __shared__ float sm[256];
    const int row = blockIdx.x;
    const int tid = threadIdx.x;

    // Max over partials
    float m = -INFINITY;
    for (int i = tid; i < NCOLTILES; i += 256)
        m = fmaxf(m, g_partials[(size_t)row * NCOLTILES + i].x);
    sm[tid] = m;
    __syncthreads();
    for (int s = 128; s > 0; s >>= 1) {
        if (tid < s) sm[tid] = fmaxf(sm[tid], sm[tid + s]);
        __syncthreads();
    }
    const float M = sm[0];
    __syncthreads();

    // Sum exp with rescale
    float acc = 0.0f;
    for (int i = tid; i < NCOLTILES; i += 256) {
        float2 p = g_partials[(size_t)row * NCOLTILES + i];
        acc += p.y * __expf(p.x - M);
    }
    sm[tid] = acc;
    __syncthreads();
    for (int s = 128; s > 0; s >>= 1) {
        if (tid < s) sm[tid] += sm[tid + s];
        __syncthreads();
    }

    if (tid == 0) {
        float logz = M + logf(sm[0]);
        // Layout sniff: int64 little-endian small positives => high words zero.
        bool is64 = ((tgt32[1] | tgt32[3] | tgt32[5] | tgt32[7]) == 0);
        int tgt = is64 ? tgt32[2 * row] : tgt32[row];
        float tl = logits[(size_t)row * VOCAB + tgt];
        g_rowloss[row] = logz - tl;
    }
}

// ---------------------------------------------------------------------------
// Kernel 3: mean over rows -> d_out[0]
// ---------------------------------------------------------------------------
__global__ __launch_bounds__(256) void finalize_kernel(float* __restrict__ out)
{
    __shared__ float sm[256];
    const int tid = threadIdx.x;
    float v = 0.0f;
    for (int i = tid; i < N_ROWS; i += 256) v += g_rowloss[i];
    sm[tid] = v;
    __syncthreads();
    for (int s = 128; s > 0; s >>= 1) {
        if (tid < s) sm[tid] += sm[tid + s];
        __syncthreads();
    }
    if (tid == 0) out[0] = sm[0] / (float)N_ROWS;
}

// ---------------------------------------------------------------------------
extern "C" void kernel_launch(void* const* d_in, const int* in_sizes, int n_in,
                              void* d_out, int out_size)
{
    const float* E   = (const float*)d_in[0];   // [N, D] f32
    const int*   tgt = (const int*)d_in[1];     // [N] int64-or-int32 (sniffed)
    const float* W   = (const float*)d_in[2];   // [V, D] f32
    const float* b   = (const float*)d_in[3];   // [V] f32
    float* out = (float*)d_out;

    // Output layout: flattened pytree (loss, logits) => loss at [0].
    const long long nv = (long long)N_ROWS * VOCAB;
    const int loss_off = ((long long)out_size == nv + 1) ? 1 : 0;
    float* logits = out + loss_off;

    dim3 grid(NCOLTILES, N_ROWS / BM);
    gemm_ce_kernel<<<grid, NTHREADS>>>(E, W, b, logits);
    row_reduce_kernel<<<N_ROWS, 256>>>(logits, tgt);
    if (loss_off == 1) finalize_kernel<<<1, 256>>>(out);
}

// round 4
// speedup vs baseline: 2.6653x; 2.6653x over previous
#include <cuda_runtime.h>
#include <cuda_bf16.h>
#include <math.h>
#include <stdint.h>

// ---------------------------------------------------------------------------
// Problem constants
// ---------------------------------------------------------------------------
#define N_ROWS    4096
#define DIM       512
#define VOCAB     128000
#define NCOLTILES 1000      // VOCAB / 128
#define NROWTILES 32        // N_ROWS / 128
#define NCHUNKS   8         // DIM / 64
#define NPSUM     (2 * NCOLTILES)   // per-warpN partial columns

// smem tile: 128 rows x 64 bf16 (128 B/row, SW128 swizzle)
#define TILE_BYTES  16384
#define STAGE_BYTES 65536   // Ahi | Alo | Bhi | Blo
#define SMEM_DYN    (2 * STAGE_BYTES + 1024)

// ---------------------------------------------------------------------------
// Device scratch (allocation-free: __device__ globals)
// ---------------------------------------------------------------------------
__device__ unsigned short g_Ehi[(size_t)N_ROWS * DIM];
__device__ unsigned short g_Elo[(size_t)N_ROWS * DIM];
__device__ unsigned short g_Whi[(size_t)VOCAB * DIM];
__device__ unsigned short g_Wlo[(size_t)VOCAB * DIM];
__device__ float g_psum[(size_t)N_ROWS * NPSUM];    // 32.8 MB
__device__ float g_rowloss[N_ROWS];

// ---------------------------------------------------------------------------
// PTX helpers
// ---------------------------------------------------------------------------
__device__ __forceinline__ uint32_t smem_u32(const void* p) {
    uint32_t a;
    asm("{ .reg .u64 t; cvta.to.shared.u64 t, %1; cvt.u32.u64 %0, t; }" : "=r"(a) : "l"(p));
    return a;
}
#define SWZ128(off) ((off) ^ (((off) >> 3) & 0x70))

__device__ __forceinline__ void cp16(uint32_t dst, const void* src) {
    asm volatile("cp.async.cg.shared.global [%0], [%1], 16;" :: "r"(dst), "l"(src));
}
#define CP_COMMIT() asm volatile("cp.async.commit_group;" ::: "memory")
#define CP_WAIT(n)  asm volatile("cp.async.wait_group %0;" :: "n"(n) : "memory")

__device__ __forceinline__ void ldmx4(uint32_t* r, uint32_t a) {
    asm volatile("ldmatrix.sync.aligned.m8n8.x4.shared.b16 {%0,%1,%2,%3}, [%4];"
                 : "=r"(r[0]), "=r"(r[1]), "=r"(r[2]), "=r"(r[3]) : "r"(a));
}
__device__ __forceinline__ void mma16816(float* d, const uint32_t* a,
                                         uint32_t b0, uint32_t b1) {
    asm volatile(
        "mma.sync.aligned.m16n8k16.row.col.f32.bf16.bf16.f32 "
        "{%0,%1,%2,%3}, {%4,%5,%6,%7}, {%8,%9}, {%0,%1,%2,%3};"
        : "+f"(d[0]), "+f"(d[1]), "+f"(d[2]), "+f"(d[3])
        : "r"(a[0]), "r"(a[1]), "r"(a[2]), "r"(a[3]), "r"(b0), "r"(b1));
}

// ---------------------------------------------------------------------------
// Split kernels: f32 -> (bf16 hi, bf16 lo = bf16(x - hi))
// ---------------------------------------------------------------------------
__device__ __forceinline__ void split4(const float4 v, unsigned short* h, unsigned short* l) {
    float xs[4] = {v.x, v.y, v.z, v.w};
    #pragma unroll
    for (int j = 0; j < 4; j++) {
        __nv_bfloat16 hb = __float2bfloat16(xs[j]);
        float r = xs[j] - __bfloat162float(hb);
        __nv_bfloat16 lb = __float2bfloat16(r);
        h[j] = *reinterpret_cast<unsigned short*>(&hb);
        l[j] = *reinterpret_cast<unsigned short*>(&lb);
    }
}
__global__ __launch_bounds__(256) void split_E_kernel(const float* __restrict__ src) {
    size_t i = (size_t)blockIdx.x * 256 + threadIdx.x;
    if (i * 4 >= (size_t)N_ROWS * DIM) return;
    unsigned short h[4], l[4];
    split4(((const float4*)src)[i], h, l);
    ((uint2*)g_Ehi)[i] = make_uint2((uint32_t)h[0] | ((uint32_t)h[1] << 16),
                                    (uint32_t)h[2] | ((uint32_t)h[3] << 16));
    ((uint2*)g_Elo)[i] = make_uint2((uint32_t)l[0] | ((uint32_t)l[1] << 16),
                                    (uint32_t)l[2] | ((uint32_t)l[3] << 16));
}
__global__ __launch_bounds__(256) void split_W_kernel(const float* __restrict__ src) {
    size_t i = (size_t)blockIdx.x * 256 + threadIdx.x;
    if (i * 4 >= (size_t)VOCAB * DIM) return;
    unsigned short h[4], l[4];
    split4(((const float4*)src)[i], h, l);
    ((uint2*)g_Whi)[i] = make_uint2((uint32_t)h[0] | ((uint32_t)h[1] << 16),
                                    (uint32_t)h[2] | ((uint32_t)h[3] << 16));
    ((uint2*)g_Wlo)[i] = make_uint2((uint32_t)l[0] | ((uint32_t)l[1] << 16),
                                    (uint32_t)l[2] | ((uint32_t)l[3] << 16));
}

// ---------------------------------------------------------------------------
// cp.async stage loader: Ahi|Alo|Bhi|Blo, 128x64 bf16 each, SW128 swizzled
// ---------------------------------------------------------------------------
__device__ __forceinline__ void load_stage(uint32_t buf_u32, int stage, int k0,
                                           int blockM, int blockN, int tid) {
    uint32_t base = buf_u32 + stage * STAGE_BYTES;
    #pragma unroll
    for (int i = 0; i < 4; i++) {
        int q = tid + i * 256;          // 0..1023
        int row = q >> 3;
        int c16 = q & 7;
        uint32_t sw = SWZ128((uint32_t)(row * 128 + c16 * 16));
        size_t eoff = (size_t)(blockM + row) * DIM + k0 + c16 * 8;
        size_t woff = (size_t)(blockN + row) * DIM + k0 + c16 * 8;
        cp16(base + 0 * TILE_BYTES + sw, &g_Ehi[eoff]);
        cp16(base + 1 * TILE_BYTES + sw, &g_Elo[eoff]);
        cp16(base + 2 * TILE_BYTES + sw, &g_Whi[woff]);
        cp16(base + 3 * TILE_BYTES + sw, &g_Wlo[woff]);
    }
    CP_COMMIT();
}

// ---------------------------------------------------------------------------
// Main HMMA GEMM + fused CE-partials kernel. CTA = 128x128 tile.
// Warps: 4x2 (M x N); warp tile 32x64; 3-term bf16 split with fp32 acc.
// ---------------------------------------------------------------------------
__global__ __launch_bounds__(256, 1) void gemm_mma_kernel(
    const float* __restrict__ bias,
    float* __restrict__ logits)
{
    extern __shared__ char dynsmem[];
    __shared__ float s_bias[128];

    const int tid  = threadIdx.x;
    const int wid  = tid >> 5;
    const int lid  = tid & 31;
    const int warpM = wid & 3;         // 0..3
    const int warpN = wid >> 2;        // 0..1
    const int blockM = blockIdx.x * 128;
    const int blockN = blockIdx.y * 128;

    uint32_t raw = smem_u32(dynsmem);
    uint32_t buf_u32 = (raw + 1023) & ~1023u;

    if (tid < 128) s_bias[tid] = bias[blockN + tid];

    float d[2][8][4];
    #pragma unroll
    for (int mt = 0; mt < 2; mt++)
        #pragma unroll
        for (int n = 0; n < 8; n++)
            #pragma unroll
            for (int c = 0; c < 4; c++) d[mt][n][c] = 0.0f;

    // ldmatrix lane addressing pieces
    const int lid15 = lid & 15;
    const int khalf = (lid >> 4) * 16;         // byte offset selecting k0-7 / k8-15
    const int rowA  = warpM * 32 + lid15;
    const int rowB  = warpN * 64 + lid15;

    load_stage(buf_u32, 0, 0, blockM, blockN, tid);

    #pragma unroll
    for (int i = 0; i < NCHUNKS; i++) {
        if (i < NCHUNKS - 1) {
            load_stage(buf_u32, (i + 1) & 1, (i + 1) * 64, blockM, blockN, tid);
            CP_WAIT(1);
        } else {
            CP_WAIT(0);
        }
        __syncthreads();

        const uint32_t sb = buf_u32 + (i & 1) * STAGE_BYTES;
        #pragma unroll
        for (int ks = 0; ks < 4; ks++) {
            const uint32_t kb = (uint32_t)(ks * 32 + khalf);
            uint32_t ah[2][4], al[2][4];
            #pragma unroll
            for (int mt = 0; mt < 2; mt++) {
                uint32_t off = SWZ128((uint32_t)((rowA + mt * 16) * 128) + kb);
                ldmx4(ah[mt], sb + off);
                ldmx4(al[mt], sb + TILE_BYTES + off);
            }
            #pragma unroll
            for (int ng = 0; ng < 4; ng++) {
                uint32_t off = SWZ128((uint32_t)((rowB + ng * 16) * 128) + kb);
                uint32_t bh[4], bl[4];
                ldmx4(bh, sb + 2 * TILE_BYTES + off);
                ldmx4(bl, sb + 3 * TILE_BYTES + off);
                #pragma unroll
                for (int mt = 0; mt < 2; mt++) {
                    mma16816(d[mt][ng * 2 + 0], ah[mt], bh[0], bh[2]);
                    mma16816(d[mt][ng * 2 + 1], ah[mt], bh[1], bh[3]);
                    mma16816(d[mt][ng * 2 + 0], ah[mt], bl[0], bl[2]);
                    mma16816(d[mt][ng * 2 + 1], ah[mt], bl[1], bl[3]);
                    mma16816(d[mt][ng * 2 + 0], al[mt], bh[0], bh[2]);
                    mma16816(d[mt][ng * 2 + 1], al[mt], bh[1], bh[3]);
                }
            }
        }
        __syncthreads();
    }

    // ---------------- epilogue: bias + exp-sum + logit stores ----------------
    const int g   = lid >> 2;    // 0..7  (row within m16 tile)
    const int tig = lid & 3;     // 0..3  (col pair selector)

    float rsum[2][2] = {{0.0f, 0.0f}, {0.0f, 0.0f}};   // [mt][row half]

    #pragma unroll
    for (int mt = 0; mt < 2; mt++) {
        const int row0 = blockM + warpM * 32 + mt * 16 + g;
        #pragma unroll
        for (int n = 0; n < 8; n++) {
            const int coll = warpN * 64 + (n >> 1) * 16 + (n & 1) * 8 + tig * 2;
            const float b0 = s_bias[coll], b1 = s_bias[coll + 1];
            float v0 = d[mt][n][0] + b0;
            float v1 = d[mt][n][1] + b1;
            float v2 = d[mt][n][2] + b0;
            float v3 = d[mt][n][3] + b1;
            rsum[mt][0] += __expf(v0) + __expf(v1);
            rsum[mt][1] += __expf(v2) + __expf(v3);
            size_t o0 = (size_t)row0 * VOCAB + blockN + coll;
            size_t o1 = (size_t)(row0 + 8) * VOCAB + blockN + coll;
            logits[o0]     = v0;
            logits[o0 + 1] = v1;
            logits[o1]     = v2;
            logits[o1 + 1] = v3;
        }
    }

    // reduce exp-sums over the 4 lanes of each quad (same rows, different cols)
    #pragma unroll
    for (int mt = 0; mt < 2; mt++)
        #pragma unroll
        for (int h = 0; h < 2; h++) {
            float s = rsum[mt][h];
            s += __shfl_xor_sync(0xFFFFFFFF, s, 1);
            s += __shfl_xor_sync(0xFFFFFFFF, s, 2);
            rsum[mt][h] = s;
        }
    if (tig == 0) {
        const int pc = blockIdx.y * 2 + warpN;
        #pragma unroll
        for (int mt = 0; mt < 2; mt++) {
            int r0 = blockM + warpM * 32 + mt * 16 + g;
            g_psum[(size_t)r0 * NPSUM + pc]       = rsum[mt][0];
            g_psum[(size_t)(r0 + 8) * NPSUM + pc] = rsum[mt][1];
        }
    }
}

// ---------------------------------------------------------------------------
// Row reduce: logz = log(sum partials); loss_row = logz - logit[target]
// ---------------------------------------------------------------------------
__global__ __launch_bounds__(256) void row_reduce_kernel(
    const float* __restrict__ logits,
    const int*   __restrict__ tgt32)
{
    __shared__ float sm[256];
    const int row = blockIdx.x;
    const int tid = threadIdx.x;
    float acc = 0.0f;
    for (int i = tid; i < NPSUM; i += 256)
        acc += g_psum[(size_t)row * NPSUM + i];
    sm[tid] = acc;
    __syncthreads();
    for (int s = 128; s > 0; s >>= 1) {
        if (tid < s) sm[tid] += sm[tid + s];
        __syncthreads();
    }
    if (tid == 0) {
        float logz = logf(sm[0]);
        bool is64 = ((tgt32[1] | tgt32[3] | tgt32[5] | tgt32[7]) == 0);
        int tgt = is64 ? tgt32[2 * row] : tgt32[row];
        g_rowloss[row] = logz - logits[(size_t)row * VOCAB + tgt];
    }
}

__global__ __launch_bounds__(256) void finalize_kernel(float* __restrict__ out) {
    __shared__ float sm[256];
    const int tid = threadIdx.x;
    float v = 0.0f;
    for (int i = tid; i < N_ROWS; i += 256) v += g_rowloss[i];
    sm[tid] = v;
    __syncthreads();
    for (int s = 128; s > 0; s >>= 1) {
        if (tid < s) sm[tid] += sm[tid + s];
        __syncthreads();
    }
    if (tid == 0) out[0] = sm[0] / (float)N_ROWS;
}

// ---------------------------------------------------------------------------
extern "C" void kernel_launch(void* const* d_in, const int* in_sizes, int n_in,
                              void* d_out, int out_size)
{
    const float* E   = (const float*)d_in[0];
    const int*   tgt = (const int*)d_in[1];
    const float* W   = (const float*)d_in[2];
    const float* b   = (const float*)d_in[3];
    float* out = (float*)d_out;

    const long long nv = (long long)N_ROWS * VOCAB;
    const int loss_off = ((long long)out_size == nv + 1) ? 1 : 0;
    float* logits = out + loss_off;

    cudaFuncSetAttribute(gemm_mma_kernel,
                         cudaFuncAttributeMaxDynamicSharedMemorySize, SMEM_DYN);

    split_E_kernel<<<(N_ROWS * DIM / 4 + 255) / 256, 256>>>(E);
    split_W_kernel<<<((size_t)VOCAB * DIM / 4 + 255) / 256, 256>>>(W);

    dim3 grid(NROWTILES, NCOLTILES);
    gemm_mma_kernel<<<grid, 256, SMEM_DYN>>>(b, logits);

    row_reduce_kernel<<<N_ROWS, 256>>>(logits, tgt);
    if (loss_off == 1) finalize_kernel<<<1, 256>>>(out);
}